// round 7
// baseline (speedup 1.0000x reference)
#include <cuda_runtime.h>
#include <cstdint>

#define N_ROWS   65536
#define DIM      256
#define NCODES   1024
#define BM       64
#define BK       64
#define XS_STR   68
#define TPB      256
#define NBLOCKS  (N_ROWS / BM)

// Scratch
__device__ float g_dictT[NCODES * DIM];     // [k][d] for coalesced gather
__device__ float g_sume2[NCODES];           // fl32 sequential sum of e^2 per code
__device__ float g_partial[NBLOCKS];        // per-block sum of squared diff

// ---------------------------------------------------------------------------
// Init A: transpose dictionary (coalesced both sides)
// ---------------------------------------------------------------------------
__global__ void vq_transpose(const float* __restrict__ dict) {
    int k = blockIdx.x;
    int d = threadIdx.x;
    g_dictT[k * DIM + d] = dict[d * NCODES + k];
}

// ---------------------------------------------------------------------------
// Init B: sum(e^2) over axis 0 — XLA column-reduce = sequential per column,
// separate mul and add roundings (no fma).
// ---------------------------------------------------------------------------
__global__ void vq_sume2(const float* __restrict__ dict) {
    int k = blockIdx.x * blockDim.x + threadIdx.x;
    if (k >= NCODES) return;
    float s = 0.0f;
    for (int d = 0; d < DIM; d++) {
        float e = dict[d * NCODES + k];
        s = __fadd_rn(s, __fmul_rn(e, e));
    }
    g_sume2[k] = s;
}

// monotone-increasing map f32 -> u32 (for argmin via unsigned min)
__device__ __forceinline__ unsigned enc_f(float s) {
    unsigned u = __float_as_uint(s);
    return (u & 0x80000000u) ? ~u : (u | 0x80000000u);
}

// ---------------------------------------------------------------------------
// Main: fused GEMM (sequential-FMA chains, matching cuBLAS/Eigen) +
//       reference-exact distance rounding + argmin(first index) +
//       gather + partial loss
// ---------------------------------------------------------------------------
// smem floats: Xs(DIM*XS_STR) Ds(DIM*XS_STR) se(NCODES) Ss(BM)
//              best(BM ull = 2*BM) codes(BM) redf(TPB)
#define SMEM_FLOATS (2 * DIM * XS_STR + NCODES + BM + 2 * BM + BM + TPB)
#define SMEM_BYTES  (SMEM_FLOATS * 4)

extern __shared__ float smem_f[];

__global__ void __launch_bounds__(TPB, 1) vq_main(const float* __restrict__ x,
                                                  const float* __restrict__ dict,
                                                  float* __restrict__ out) {
    float* Xs = smem_f;
    float* Ds = Xs + DIM * XS_STR;
    float* se = Ds + DIM * XS_STR;
    float* Ss = se + NCODES;
    unsigned long long* best = (unsigned long long*)(Ss + BM);
    int*   codes = (int*)(best + BM);
    float* redf  = (float*)(codes + BM);

    const int tid = threadIdx.x;
    const int m0  = blockIdx.x * BM;

    // --- load x tile, store transposed [d][m] ---
    const float4* x4 = (const float4*)(x + (size_t)m0 * DIM);
    #pragma unroll 4
    for (int t = tid; t < BM * DIM / 4; t += TPB) {
        int m  = t >> 6;
        int c4 = t & 63;
        float4 v = x4[t];
        int d = c4 * 4;
        Xs[(d + 0) * XS_STR + m] = v.x;
        Xs[(d + 1) * XS_STR + m] = v.y;
        Xs[(d + 2) * XS_STR + m] = v.z;
        Xs[(d + 3) * XS_STR + m] = v.w;
    }
    for (int i = tid; i < NCODES; i += TPB) se[i] = g_sume2[i];
    if (tid < BM) best[tid] = 0xFFFFFFFFFFFFFFFFull;
    __syncthreads();

    // --- S = sum(x_row^2), emulating XLA GPU warp row-reduce:
    //     lane t accumulates d = t, t+32, ..., t+224 (mul+add, no fma),
    //     then shfl tree 16/8/4/2/1; lane 0's value is the reference value.
    {
        int warp = tid >> 5, lane = tid & 31;
        #pragma unroll
        for (int r = 0; r < BM / 8; r++) {
            int row = warp * (BM / 8) + r;
            float p = 0.0f;
            #pragma unroll
            for (int i = 0; i < 8; i++) {
                float v = Xs[(lane + 32 * i) * XS_STR + row];
                p = __fadd_rn(p, __fmul_rn(v, v));
            }
            #pragma unroll
            for (int o = 16; o > 0; o >>= 1)
                p = __fadd_rn(p, __shfl_xor_sync(0xFFFFFFFFu, p, o));
            if (lane == 0) Ss[row] = p;   // lane-0 grouping == shfl_down tree
        }
    }
    __syncthreads();

    const int tx = tid & 15;   // code group (16 x 4 = 64 codes)
    const int ty = tid >> 4;   // row group  (16 x 4 = 64 rows)

    float Srow[4];
    #pragma unroll
    for (int i = 0; i < 4; i++) Srow[i] = Ss[ty * 4 + i];

    // per-thread running argmin key per row: (enc(dist)<<32 | k), min wins
    unsigned long long kmin[4] = {0xFFFFFFFFFFFFFFFFull, 0xFFFFFFFFFFFFFFFFull,
                                  0xFFFFFFFFFFFFFFFFull, 0xFFFFFFFFFFFFFFFFull};

    for (int kc = 0; kc < NCODES / BK; kc++) {
        #pragma unroll 4
        for (int t = tid; t < DIM * BK; t += TPB) {
            int d = t >> 6;
            int k = t & 63;
            Ds[d * XS_STR + k] = dict[d * NCODES + kc * BK + k];
        }
        __syncthreads();

        // sim: single sequential FFMA chain over d=0..255 per output
        float acc[4][4] = {};
        #pragma unroll 8
        for (int d = 0; d < DIM; d++) {
            float4 a = *(const float4*)&Xs[d * XS_STR + ty * 4];
            float4 b = *(const float4*)&Ds[d * XS_STR + tx * 4];
            acc[0][0] += a.x * b.x; acc[0][1] += a.x * b.y; acc[0][2] += a.x * b.z; acc[0][3] += a.x * b.w;
            acc[1][0] += a.y * b.x; acc[1][1] += a.y * b.y; acc[1][2] += a.y * b.z; acc[1][3] += a.y * b.w;
            acc[2][0] += a.z * b.x; acc[2][1] += a.z * b.y; acc[2][2] += a.z * b.z; acc[2][3] += a.z * b.w;
            acc[3][0] += a.w * b.x; acc[3][1] += a.w * b.y; acc[3][2] += a.w * b.z; acc[3][3] += a.w * b.w;
        }

        // reference-exact distance: D = fl( fl(S + se_k) - 2*sim )
        #pragma unroll
        for (int i = 0; i < 4; i++) {
            #pragma unroll
            for (int j = 0; j < 4; j++) {
                int k = kc * BK + tx * 4 + j;
                float T = __fadd_rn(Srow[i], se[k]);       // rounds at ~256
                float D = __fadd_rn(T, -2.0f * acc[i][j]); // 2*sim exact; one rounding
                unsigned long long key =
                    ((unsigned long long)enc_f(D) << 32) | (unsigned long long)(unsigned)k;
                if (key < kmin[i]) kmin[i] = key;
            }
        }
        __syncthreads();   // protects Ds reuse
    }

    // merge per-thread argmin (min key == min dist, tie -> smallest k)
    #pragma unroll
    for (int i = 0; i < 4; i++) atomicMin(&best[ty * 4 + i], kmin[i]);
    __syncthreads();

    if (tid < BM)
        codes[tid] = (int)(unsigned)(best[tid] & 0xFFFFFFFFull);
    __syncthreads();

    // --- gather quantized rows + partial squared-diff sum ---
    float lsum = 0.0f;
    #pragma unroll 4
    for (int t = tid; t < BM * DIM; t += TPB) {
        int m = t >> 8;
        int d = t & 255;
        float val = g_dictT[codes[m] * DIM + d];
        float xv  = Xs[d * XS_STR + m];
        float df  = xv - val;
        lsum += df * df;
        out[(size_t)(m0 + m) * DIM + d] = val;
    }
    redf[tid] = lsum;
    __syncthreads();
    #pragma unroll
    for (int s = TPB / 2; s > 0; s >>= 1) {
        if (tid < s) redf[tid] += redf[tid + s];
        __syncthreads();
    }
    if (tid == 0) g_partial[blockIdx.x] = redf[0];
}

// ---------------------------------------------------------------------------
// Final loss: loss = fl( m + fl(0.25*m) ), m = mean((x-q)^2) (f64 reduce)
// ---------------------------------------------------------------------------
__global__ void vq_finish(float* __restrict__ out, int out_size) {
    __shared__ double rd[TPB];
    int tid = threadIdx.x;
    double s = 0.0;
    for (int i = tid; i < NBLOCKS; i += TPB) s += (double)g_partial[i];
    rd[tid] = s;
    __syncthreads();
    #pragma unroll
    for (int st = TPB / 2; st > 0; st >>= 1) {
        if (tid < st) rd[tid] += rd[tid + st];
        __syncthreads();
    }
    if (tid == 0 && out_size > N_ROWS * DIM) {
        double mse = rd[0] / (double)((size_t)N_ROWS * DIM);
        float m = (float)mse;
        out[N_ROWS * DIM] = __fadd_rn(m, __fmul_rn(0.25f, m));
    }
}

// ---------------------------------------------------------------------------
extern "C" void kernel_launch(void* const* d_in, const int* in_sizes, int n_in,
                              void* d_out, int out_size) {
    const float* x    = (const float*)d_in[0];   // [16,64,64,256] f32
    const float* dict = (const float*)d_in[1];   // [256,1024]     f32
    float* out = (float*)d_out;

    cudaFuncSetAttribute(vq_main, cudaFuncAttributeMaxDynamicSharedMemorySize, SMEM_BYTES);

    vq_transpose<<<NCODES, DIM>>>(dict);
    vq_sume2<<<NCODES / TPB, TPB>>>(dict);
    vq_main<<<NBLOCKS, TPB, SMEM_BYTES>>>(x, dict, out);
    vq_finish<<<1, TPB>>>(out, out_size);
}

// round 8
// speedup vs baseline: 1.4349x; 1.4349x over previous
#include <cuda_runtime.h>
#include <cstdint>

#define N_ROWS      65536
#define DIM         256
#define NCODES      1024
#define BM          128
#define BK          64
#define HALF_CODES  512
#define XS_STR      132          // 128 + 4 pad (floats), keeps 16B alignment
#define DS_STR      68           // 64 + 4 pad
#define TPB         256
#define NTILES      (N_ROWS / BM)        // 512 row tiles
#define NBLOCKS_MAIN (NTILES * 2)        // x2 code halves = 1024 blocks

// Scratch (no allocation allowed anywhere)
__device__ float g_dictT[NCODES * DIM];            // [k][d] for coalesced gather
__device__ float g_sume2[NCODES];                  // fl32 sequential sum e^2 per code
__device__ unsigned long long g_best[N_ROWS];      // global argmin keys
__device__ float g_partial[NTILES];                // per-tile loss partials

// ---------------------------------------------------------------------------
// Init A: transpose dictionary
// ---------------------------------------------------------------------------
__global__ void vq_transpose(const float* __restrict__ dict) {
    int k = blockIdx.x;
    int d = threadIdx.x;
    g_dictT[k * DIM + d] = dict[d * NCODES + k];
}

// ---------------------------------------------------------------------------
// Init B: sum(e^2) axis 0 — sequential, separate mul/add roundings (no fma)
// ---------------------------------------------------------------------------
__global__ void vq_sume2(const float* __restrict__ dict) {
    int k = blockIdx.x * blockDim.x + threadIdx.x;
    if (k >= NCODES) return;
    float s = 0.0f;
    for (int d = 0; d < DIM; d++) {
        float e = dict[d * NCODES + k];
        s = __fadd_rn(s, __fmul_rn(e, e));
    }
    g_sume2[k] = s;
}

// ---------------------------------------------------------------------------
// Init C: reset global argmin keys (graph replays -> must reset every launch)
// ---------------------------------------------------------------------------
__global__ void vq_reset() {
    int i = blockIdx.x * blockDim.x + threadIdx.x;
    g_best[i] = 0xFFFFFFFFFFFFFFFFull;
}

// monotone-increasing map f32 -> u32 (argmin via unsigned min)
__device__ __forceinline__ unsigned enc_f(float s) {
    unsigned u = __float_as_uint(s);
    return (u & 0x80000000u) ? ~u : (u | 0x80000000u);
}

// packed helpers
__device__ __forceinline__ unsigned long long bcast2(float v) {
    unsigned long long r;
    asm("mov.b64 %0, {%1, %1};" : "=l"(r) : "f"(v));
    return r;
}
__device__ __forceinline__ void ffma2(unsigned long long& acc,
                                      unsigned long long a, unsigned long long b) {
    // packed f32x2 FMA: each lane IEEE rn — bitwise identical to two FFMAs
    asm("fma.rn.f32x2 %0, %1, %2, %0;" : "+l"(acc) : "l"(a), "l"(b));
}
__device__ __forceinline__ void unpack2(unsigned long long p, float& lo, float& hi) {
    asm("mov.b64 {%0, %1}, %2;" : "=f"(lo), "=f"(hi) : "l"(p));
}

// ---------------------------------------------------------------------------
// Main: 128-row x 512-code tile per block. Packed-FFMA2 GEMM with per-output
// sequential d=0..255 chains (bit-identical to reference), reference-exact
// distance rounding, argmin -> global atomicMin keys.
// ---------------------------------------------------------------------------
// smem floats: Xs(DIM*XS_STR) Ds(DIM*DS_STR) se(NCODES) Ss(BM) bestsh(BM ull)
#define SMEM_FLOATS (DIM * XS_STR + DIM * DS_STR + NCODES + BM + 2 * BM)
#define SMEM_BYTES  (SMEM_FLOATS * 4)

extern __shared__ float smem_f[];

__global__ void __launch_bounds__(TPB, 1) vq_main(const float* __restrict__ x,
                                                  const float* __restrict__ dict) {
    float* Xs = smem_f;
    float* Ds = Xs + DIM * XS_STR;
    float* se = Ds + DIM * DS_STR;
    float* Ss = se + NCODES;
    unsigned long long* bestsh = (unsigned long long*)(Ss + BM);

    const int tid  = threadIdx.x;
    const int rt   = blockIdx.x >> 1;        // row tile
    const int half = blockIdx.x & 1;         // code half
    const int m0   = rt * BM;
    const int k0   = half * HALF_CODES;

    // --- load x tile [BM][DIM], store transposed [d][m] ---
    const float4* x4 = (const float4*)(x + (size_t)m0 * DIM);
    #pragma unroll 4
    for (int t = tid; t < BM * DIM / 4; t += TPB) {
        int m  = t >> 6;          // 64 float4 per row
        int c4 = t & 63;
        float4 v = x4[t];
        int d = c4 * 4;
        Xs[(d + 0) * XS_STR + m] = v.x;
        Xs[(d + 1) * XS_STR + m] = v.y;
        Xs[(d + 2) * XS_STR + m] = v.z;
        Xs[(d + 3) * XS_STR + m] = v.w;
    }
    for (int i = tid; i < NCODES; i += TPB) se[i] = g_sume2[i];
    if (tid < BM) bestsh[tid] = 0xFFFFFFFFFFFFFFFFull;
    __syncthreads();

    // --- S = sum(x_row^2): exact same emulation as R7 (XLA warp row-reduce):
    //     lane t sums d = t, t+32, ..., t+224 (mul+add, no fma), shfl tree.
    {
        int warp = tid >> 5, lane = tid & 31;
        #pragma unroll
        for (int r = 0; r < BM / 8; r++) {          // 8 warps x 16 rows
            int row = warp * (BM / 8) + r;
            float p = 0.0f;
            #pragma unroll
            for (int i = 0; i < 8; i++) {
                float v = Xs[(lane + 32 * i) * XS_STR + row];
                p = __fadd_rn(p, __fmul_rn(v, v));
            }
            #pragma unroll
            for (int o = 16; o > 0; o >>= 1)
                p = __fadd_rn(p, __shfl_xor_sync(0xFFFFFFFFu, p, o));
            if (lane == 0) Ss[row] = p;
        }
    }
    __syncthreads();

    const int tx = tid & 15;    // 16 code groups x 4 codes = 64 (BK)
    const int ty = tid >> 4;    // 16 row groups  x 8 rows  = 128 (BM)

    float Srow[8];
    #pragma unroll
    for (int i = 0; i < 8; i++) Srow[i] = Ss[ty * 8 + i];

    unsigned long long kmin[8];
    #pragma unroll
    for (int i = 0; i < 8; i++) kmin[i] = 0xFFFFFFFFFFFFFFFFull;

    for (int kc = 0; kc < HALF_CODES / BK; kc++) {
        // load dict chunk [DIM][BK], coalesced
        #pragma unroll 4
        for (int t = tid; t < DIM * BK; t += TPB) {
            int d = t >> 6;
            int k = t & 63;
            Ds[d * DS_STR + k] = dict[d * NCODES + k0 + kc * BK + k];
        }
        __syncthreads();

        // packed accumulators: acc2[rowpair][code]; each packed lane is one
        // row's sequential FFMA chain over d = 0..255 (order == reference)
        unsigned long long acc2[4][4];
        #pragma unroll
        for (int i = 0; i < 4; i++)
            #pragma unroll
            for (int j = 0; j < 4; j++) acc2[i][j] = 0ULL;

        #pragma unroll 4
        for (int d = 0; d < DIM; d++) {
            ulonglong2 a01 = *(const ulonglong2*)&Xs[d * XS_STR + ty * 8];
            ulonglong2 a23 = *(const ulonglong2*)&Xs[d * XS_STR + ty * 8 + 4];
            float4 b = *(const float4*)&Ds[d * DS_STR + tx * 4];
            unsigned long long b0 = bcast2(b.x);
            unsigned long long b1 = bcast2(b.y);
            unsigned long long b2 = bcast2(b.z);
            unsigned long long b3 = bcast2(b.w);
            ffma2(acc2[0][0], a01.x, b0); ffma2(acc2[0][1], a01.x, b1);
            ffma2(acc2[0][2], a01.x, b2); ffma2(acc2[0][3], a01.x, b3);
            ffma2(acc2[1][0], a01.y, b0); ffma2(acc2[1][1], a01.y, b1);
            ffma2(acc2[1][2], a01.y, b2); ffma2(acc2[1][3], a01.y, b3);
            ffma2(acc2[2][0], a23.x, b0); ffma2(acc2[2][1], a23.x, b1);
            ffma2(acc2[2][2], a23.x, b2); ffma2(acc2[2][3], a23.x, b3);
            ffma2(acc2[3][0], a23.y, b0); ffma2(acc2[3][1], a23.y, b1);
            ffma2(acc2[3][2], a23.y, b2); ffma2(acc2[3][3], a23.y, b3);
        }

        // reference-exact distance: D = fl( fl(S + se_k) - 2*sim )
        #pragma unroll
        for (int rp = 0; rp < 4; rp++) {
            #pragma unroll
            for (int j = 0; j < 4; j++) {
                int k = k0 + kc * BK + tx * 4 + j;
                float slo, shi;
                unpack2(acc2[rp][j], slo, shi);
                float T0 = __fadd_rn(Srow[rp * 2 + 0], se[k]);
                float D0 = __fadd_rn(T0, -2.0f * slo);
                unsigned long long key0 =
                    ((unsigned long long)enc_f(D0) << 32) | (unsigned long long)(unsigned)k;
                if (key0 < kmin[rp * 2 + 0]) kmin[rp * 2 + 0] = key0;
                float T1 = __fadd_rn(Srow[rp * 2 + 1], se[k]);
                float D1 = __fadd_rn(T1, -2.0f * shi);
                unsigned long long key1 =
                    ((unsigned long long)enc_f(D1) << 32) | (unsigned long long)(unsigned)k;
                if (key1 < kmin[rp * 2 + 1]) kmin[rp * 2 + 1] = key1;
            }
        }
        __syncthreads();   // protects Ds reuse
    }

    // block-local merge (order-independent min), then one global atomic per row
    #pragma unroll
    for (int i = 0; i < 8; i++) atomicMin(&bestsh[ty * 8 + i], kmin[i]);
    __syncthreads();
    if (tid < BM) atomicMin(&g_best[m0 + tid], bestsh[tid]);
}

// ---------------------------------------------------------------------------
// Gather: codes -> quantized output + per-tile loss partial (deterministic)
// ---------------------------------------------------------------------------
__global__ void __launch_bounds__(TPB) vq_gather(const float* __restrict__ x,
                                                 float* __restrict__ out) {
    __shared__ int codes[BM];
    __shared__ float redf[TPB];
    const int tid = threadIdx.x;
    const int m0  = blockIdx.x * BM;

    if (tid < BM)
        codes[tid] = (int)(unsigned)(g_best[m0 + tid] & 0xFFFFFFFFull);
    __syncthreads();

    const float4* x4 = (const float4*)x;
    float4* out4 = (float4*)out;
    float lsum = 0.0f;
    #pragma unroll 4
    for (int t = tid; t < BM * DIM / 4; t += TPB) {
        int m  = t >> 6;
        int d4 = t & 63;
        float4 v  = *(const float4*)&g_dictT[codes[m] * DIM + d4 * 4];
        size_t gi = (size_t)(m0 + m) * (DIM / 4) + d4;
        float4 xv = x4[gi];
        float dx = xv.x - v.x, dy = xv.y - v.y, dz = xv.z - v.z, dw = xv.w - v.w;
        lsum += dx * dx + dy * dy + dz * dz + dw * dw;
        out4[gi] = v;
    }
    redf[tid] = lsum;
    __syncthreads();
    #pragma unroll
    for (int s = TPB / 2; s > 0; s >>= 1) {
        if (tid < s) redf[tid] += redf[tid + s];
        __syncthreads();
    }
    if (tid == 0) g_partial[blockIdx.x] = redf[0];
}

// ---------------------------------------------------------------------------
// Final loss: loss = fl( m + fl(0.25*m) ), m = mean((x-q)^2) (f64 reduce)
// ---------------------------------------------------------------------------
__global__ void vq_finish(float* __restrict__ out, int out_size) {
    __shared__ double rd[TPB];
    int tid = threadIdx.x;
    double s = 0.0;
    for (int i = tid; i < NTILES; i += TPB) s += (double)g_partial[i];
    rd[tid] = s;
    __syncthreads();
    #pragma unroll
    for (int st = TPB / 2; st > 0; st >>= 1) {
        if (tid < st) rd[tid] += rd[tid + st];
        __syncthreads();
    }
    if (tid == 0 && out_size > N_ROWS * DIM) {
        double mse = rd[0] / (double)((size_t)N_ROWS * DIM);
        float m = (float)mse;
        out[N_ROWS * DIM] = __fadd_rn(m, __fmul_rn(0.25f, m));
    }
}

// ---------------------------------------------------------------------------
extern "C" void kernel_launch(void* const* d_in, const int* in_sizes, int n_in,
                              void* d_out, int out_size) {
    const float* x    = (const float*)d_in[0];   // [16,64,64,256] f32
    const float* dict = (const float*)d_in[1];   // [256,1024]     f32
    float* out = (float*)d_out;

    cudaFuncSetAttribute(vq_main, cudaFuncAttributeMaxDynamicSharedMemorySize, SMEM_BYTES);

    vq_transpose<<<NCODES, DIM>>>(dict);
    vq_sume2<<<NCODES / TPB, TPB>>>(dict);
    vq_reset<<<N_ROWS / TPB, TPB>>>();
    vq_main<<<NBLOCKS_MAIN, TPB, SMEM_BYTES>>>(x, dict);
    vq_gather<<<NTILES, TPB>>>(x, out);
    vq_finish<<<1, TPB>>>(out, out_size);
}